// round 3
// baseline (speedup 1.0000x reference)
#include <cuda_runtime.h>
#include <cuda_bf16.h>
#include <cstdint>

#define Bsz 64
#define Ssz 64
#define Hsz 1024
#define Vsz 32000
#define Tsz 40

// out layout: logits [B,T,V] | hidden [1,B,H] | attn [B,T,S]
#define OUT_LOGITS 0L
#define OUT_HIDDEN 81920000L
#define OUT_ATTN   81985536L

// ----------------------------- device scratch ------------------------------
__device__ float g_Wcat [4096 * 1024];   // [Wa ; W_hh]
__device__ float g_bcat [4096];          // [ba ; b_hh]
__device__ float g_keysU[Bsz * Ssz * Hsz];
__device__ float g_h    [Bsz * Hsz];
__device__ float g_x    [Bsz * 2 * Hsz]; // [emb | ctx]
__device__ float g_qgh  [Bsz * 4096];    // [q | ghr | ghz | ghn]
__device__ float g_gi   [Bsz * 3072];
__device__ float g_Hall [Bsz * Tsz * Hsz];

// ----------------------------- helpers -------------------------------------
__device__ __forceinline__ float tanha(float x) {
    float r; asm("tanh.approx.f32 %0, %1;" : "=f"(r) : "f"(x)); return r;
}
__device__ __forceinline__ float sigm(float x) { return 0.5f * tanha(0.5f * x) + 0.5f; }

__device__ __forceinline__ void mma_tf32(float* c, const uint32_t* a, const uint32_t* b) {
    asm volatile(
        "mma.sync.aligned.m16n8k8.row.col.f32.tf32.tf32.f32 "
        "{%0,%1,%2,%3}, {%4,%5,%6,%7}, {%8,%9}, {%0,%1,%2,%3};"
        : "+f"(c[0]), "+f"(c[1]), "+f"(c[2]), "+f"(c[3])
        : "r"(a[0]), "r"(a[1]), "r"(a[2]), "r"(a[3]), "r"(b[0]), "r"(b[1]));
}

// ----------------------------- setup ---------------------------------------
// copies Wa,W_hh -> g_Wcat ; ba,b_hh -> g_bcat ; encoder_hidden -> g_h
__global__ void setup_kernel(const float* __restrict__ Wa, const float* __restrict__ Whh,
                             const float* __restrict__ ba, const float* __restrict__ bhh,
                             const float* __restrict__ ehid)
{
    long i = (long)blockIdx.x * 256 + threadIdx.x;
    if (i < 1048576L)        g_Wcat[i] = Wa[i];
    else if (i < 4194304L)   g_Wcat[i] = Whh[i - 1048576L];
    else if (i < 4198400L) { long j = i - 4194304L; g_bcat[j] = (j < 1024) ? ba[j] : bhh[j - 1024]; }
    else if (i < 4263936L) { long j = i - 4198400L; g_h[j] = ehid[j]; }
}

// ----------------------------- tf32 GEMM -----------------------------------
// C[M,N] = A[M,K] @ B[N,K]^T + bias.  BM=BN=64, BK=32, 128 threads (4 warps).
// M,N multiples of 64; K multiple of 32 (true for all call sites). No bounds checks.
__global__ void __launch_bounds__(128) gemm_tf32(
    const float* __restrict__ A, const float* __restrict__ B,
    const float* __restrict__ bias, float* __restrict__ C,
    int M, int N, int K)
{
    __shared__ __align__(16) float As[64][36];
    __shared__ __align__(16) float Bs[64][36];
    int tid  = threadIdx.x;
    int warp = tid >> 5, lane = tid & 31;
    int wm = warp >> 1, wn = warp & 1;
    int bm = blockIdx.x * 64, bn = blockIdx.y * 64;

    float c[2][4][4];
#pragma unroll
    for (int i = 0; i < 2; i++)
#pragma unroll
        for (int j = 0; j < 4; j++)
#pragma unroll
            for (int r = 0; r < 4; r++) c[i][j][r] = 0.f;

    int lr = tid >> 1;          // tile row 0..63
    int lc = (tid & 1) * 16;    // 0 or 16
    const float* Ag = A + (long)(bm + lr) * K + lc;
    const float* Bg = B + (long)(bn + lr) * K + lc;

    for (int kt = 0; kt < K; kt += 32) {
#pragma unroll
        for (int u = 0; u < 4; u++) {
            *(float4*)&As[lr][lc + u * 4] = *(const float4*)(Ag + kt + u * 4);
            *(float4*)&Bs[lr][lc + u * 4] = *(const float4*)(Bg + kt + u * 4);
        }
        __syncthreads();
#pragma unroll
        for (int ks = 0; ks < 4; ks++) {
            int k0 = ks * 8;
            uint32_t af[2][4], bf[4][2];
#pragma unroll
            for (int i = 0; i < 2; i++) {
                int r0 = wm * 32 + i * 16 + (lane >> 2);
                int cc = k0 + (lane & 3);
                af[i][0] = __float_as_uint(As[r0    ][cc    ]);
                af[i][1] = __float_as_uint(As[r0 + 8][cc    ]);
                af[i][2] = __float_as_uint(As[r0    ][cc + 4]);
                af[i][3] = __float_as_uint(As[r0 + 8][cc + 4]);
            }
#pragma unroll
            for (int j = 0; j < 4; j++) {
                int n0 = wn * 32 + j * 8 + (lane >> 2);
                int kk = k0 + (lane & 3);
                bf[j][0] = __float_as_uint(Bs[n0][kk    ]);
                bf[j][1] = __float_as_uint(Bs[n0][kk + 4]);
            }
#pragma unroll
            for (int i = 0; i < 2; i++)
#pragma unroll
                for (int j = 0; j < 4; j++)
                    mma_tf32(c[i][j], af[i], bf[j]);
        }
        __syncthreads();
    }

#pragma unroll
    for (int i = 0; i < 2; i++) {
        int r0 = bm + wm * 32 + i * 16 + (lane >> 2);
#pragma unroll
        for (int j = 0; j < 4; j++) {
            int c0 = bn + wn * 32 + j * 8 + (lane & 3) * 2;
            float b0 = bias ? bias[c0]     : 0.f;
            float b1 = bias ? bias[c0 + 1] : 0.f;
            C[(long)r0 * N + c0]           = c[i][j][0] + b0;
            C[(long)r0 * N + c0 + 1]       = c[i][j][1] + b1;
            C[(long)(r0 + 8) * N + c0]     = c[i][j][2] + b0;
            C[(long)(r0 + 8) * N + c0 + 1] = c[i][j][3] + b1;
        }
    }
}

// ----------------------------- attention + embed ---------------------------
// one block per batch b: scores -> softmax -> ctx; writes attn weights to out,
// and fills g_x = [embedding[token_t] | ctx]
__global__ void __launch_bounds__(256) attn_kernel(
    const float* __restrict__ enc, const float* __restrict__ Va,
    const float* __restrict__ bv, const int* __restrict__ target,
    const float* __restrict__ emb, float* __restrict__ out_attn, int t)
{
    int b = blockIdx.x, tid = threadIdx.x;
    __shared__ float qs[Hsz];
    __shared__ float sc[Ssz];
    for (int h = tid; h < Hsz; h += 256) qs[h] = g_qgh[b * 4096 + h];
    __syncthreads();

    int warp = tid >> 5, lane = tid & 31;
    for (int s = warp; s < Ssz; s += 8) {
        const float* kr = g_keysU + ((long)b * Ssz + s) * Hsz;
        float acc = 0.f;
        for (int h = lane; h < Hsz; h += 32)
            acc += tanha(qs[h] + kr[h]) * Va[h];
        for (int o = 16; o; o >>= 1) acc += __shfl_xor_sync(~0u, acc, o);
        if (lane == 0) sc[s] = acc + bv[0];
    }
    __syncthreads();

    if (warp == 0) {
        float v0 = sc[lane], v1 = sc[lane + 32];
        float m = fmaxf(v0, v1);
        for (int o = 16; o; o >>= 1) m = fmaxf(m, __shfl_xor_sync(~0u, m, o));
        float e0 = __expf(v0 - m), e1 = __expf(v1 - m);
        float ssum = e0 + e1;
        for (int o = 16; o; o >>= 1) ssum += __shfl_xor_sync(~0u, ssum, o);
        float inv = 1.f / ssum;
        sc[lane] = e0 * inv; sc[lane + 32] = e1 * inv;
        long ob = ((long)b * Tsz + t) * Ssz;
        out_attn[ob + lane]      = e0 * inv;
        out_attn[ob + lane + 32] = e1 * inv;
    }
    __syncthreads();

    // ctx: each thread owns 4 contiguous h
    int h0 = tid * 4;
    float4 acc = {0.f, 0.f, 0.f, 0.f};
    const float* eb = enc + (long)b * Ssz * Hsz + h0;
#pragma unroll 4
    for (int s = 0; s < Ssz; s++) {
        float w = sc[s];
        float4 e = *(const float4*)(eb + (long)s * Hsz);
        acc.x += w * e.x; acc.y += w * e.y; acc.z += w * e.z; acc.w += w * e.w;
    }
    *(float4*)&g_x[b * 2048 + Hsz + h0] = acc;

    int tok = (t == 0) ? 0 : target[b * Tsz + (t - 1)];
    *(float4*)&g_x[b * 2048 + h0] = *(const float4*)(emb + (long)tok * Hsz + h0);
}

// ----------------------------- GRU gates -----------------------------------
__global__ void __launch_bounds__(256) gates_kernel(float* __restrict__ out_hidden, int t)
{
    int b = blockIdx.x, tid = threadIdx.x;
    for (int h = tid; h < Hsz; h += 256) {
        float ir = g_gi[b * 3072 + h];
        float iz = g_gi[b * 3072 + 1024 + h];
        float in_ = g_gi[b * 3072 + 2048 + h];
        float hr = g_qgh[b * 4096 + 1024 + h];
        float hz = g_qgh[b * 4096 + 2048 + h];
        float hn = g_qgh[b * 4096 + 3072 + h];
        float r = sigm(ir + hr);
        float z = sigm(iz + hz);
        float n = tanha(in_ + r * hn);
        float hnew = (1.f - z) * n + z * g_h[b * Hsz + h];
        g_h[b * Hsz + h] = hnew;
        g_Hall[((long)b * Tsz + t) * Hsz + h] = hnew;
        if (t == Tsz - 1) out_hidden[b * Hsz + h] = hnew;
    }
}

// ----------------------------- log-softmax ---------------------------------
// one block per row of [2560, 32000]; online max/sum, then subtract logZ.
__global__ void __launch_bounds__(256) logsoftmax_kernel(float* __restrict__ logits)
{
    float* p = logits + (long)blockIdx.x * Vsz;
    int tid = threadIdx.x;
    float m = -1e30f, s = 0.f;
    for (int i = tid; i < Vsz; i += 256) {
        float v = p[i];
        if (v > m) { s = s * __expf(m - v) + 1.f; m = v; }
        else       { s += __expf(v - m); }
    }
    __shared__ float sm[256], ss[256];
    sm[tid] = m; ss[tid] = s; __syncthreads();
    for (int o = 128; o; o >>= 1) {
        if (tid < o) {
            float m2 = sm[tid + o], s2 = ss[tid + o];
            float M = fmaxf(sm[tid], m2);
            ss[tid] = ss[tid] * __expf(sm[tid] - M) + s2 * __expf(m2 - M);
            sm[tid] = M;
        }
        __syncthreads();
    }
    float logZ = sm[0] + logf(ss[0]);
    for (int i = tid; i < Vsz; i += 256) p[i] -= logZ;
}

// ----------------------------- launch --------------------------------------
extern "C" void kernel_launch(void* const* d_in, const int* in_sizes, int n_in,
                              void* d_out, int out_size)
{
    (void)in_sizes; (void)n_in; (void)out_size;
    const float* enc   = (const float*)d_in[0];
    const float* ehid  = (const float*)d_in[1];
    const int*   targ  = (const int*)  d_in[2];
    const float* emb   = (const float*)d_in[3];
    const float* Wa    = (const float*)d_in[4];
    const float* ba    = (const float*)d_in[5];
    const float* Ua    = (const float*)d_in[6];
    const float* bu    = (const float*)d_in[7];
    const float* Va    = (const float*)d_in[8];
    const float* bv    = (const float*)d_in[9];
    const float* W_ih  = (const float*)d_in[10];
    const float* W_hh  = (const float*)d_in[11];
    const float* b_ih  = (const float*)d_in[12];
    const float* b_hh  = (const float*)d_in[13];
    const float* W_out = (const float*)d_in[14];
    const float* b_out = (const float*)d_in[15];
    float* out = (float*)d_out;

    float *pWcat, *pbcat, *pkeysU, *ph, *px, *pqgh, *pgi, *pHall;
    cudaGetSymbolAddress((void**)&pWcat,  g_Wcat);
    cudaGetSymbolAddress((void**)&pbcat,  g_bcat);
    cudaGetSymbolAddress((void**)&pkeysU, g_keysU);
    cudaGetSymbolAddress((void**)&ph,     g_h);
    cudaGetSymbolAddress((void**)&px,     g_x);
    cudaGetSymbolAddress((void**)&pqgh,   g_qgh);
    cudaGetSymbolAddress((void**)&pgi,    g_gi);
    cudaGetSymbolAddress((void**)&pHall,  g_Hall);

    setup_kernel<<<(4263936 + 255) / 256, 256>>>(Wa, W_hh, ba, b_hh, ehid);

    // keysU = enc @ Ua^T + bu : [4096,1024] x [1024,1024]^T
    gemm_tf32<<<dim3(64, 16), 128>>>(enc, Ua, bu, pkeysU, 4096, 1024, 1024);

    for (int t = 0; t < Tsz; t++) {
        // [q | gh] = h @ [Wa;W_hh]^T + [ba;b_hh] : [64,4096]
        gemm_tf32<<<dim3(1, 64), 128>>>(ph, pWcat, pbcat, pqgh, 64, 4096, 1024);
        attn_kernel<<<Bsz, 256>>>(enc, Va, bv, targ, emb, out + OUT_ATTN, t);
        // gi = x @ W_ih^T + b_ih : [64,3072], K=2048
        gemm_tf32<<<dim3(1, 48), 128>>>(px, W_ih, b_ih, pgi, 64, 3072, 2048);
        gates_kernel<<<Bsz, 256>>>(out + OUT_HIDDEN, t);
    }

    // logits = H_all @ W_out^T + b_out : [2560, 32000], K=1024
    gemm_tf32<<<dim3(40, 500), 128>>>(pHall, W_out, b_out, out + OUT_LOGITS,
                                      2560, 32000, 1024);
    logsoftmax_kernel<<<Bsz * Tsz, 256>>>(out + OUT_LOGITS);
}

// round 6
// speedup vs baseline: 1.4255x; 1.4255x over previous
#include <cuda_runtime.h>
#include <cuda_bf16.h>
#include <cstdint>

#define Bsz 64
#define Ssz 64
#define Hsz 1024
#define Vsz 32000
#define Tsz 40
#define KS  4                    // split-K factor for per-step GEMMs

// out layout: logits [B,T,V] | hidden [1,B,H] | attn [B,T,S]
#define OUT_LOGITS 0L
#define OUT_HIDDEN 81920000L
#define OUT_ATTN   81985536L

// ----------------------------- device scratch ------------------------------
__device__ float          g_Wcat [4096 * 1024];        // [Wa ; W_hh]
__device__ float          g_keysU[Bsz * Ssz * Hsz];
__device__ float          g_h    [Bsz * Hsz];
__device__ float          g_x    [Bsz * 2 * Hsz];      // [emb | ctx]
__device__ float          g_qgh  [KS * Bsz * 4096];    // split-K slabs
__device__ float          g_gi   [KS * Bsz * 3072];    // split-K slabs
__device__ __nv_bfloat16  g_Hall [Bsz * Tsz * Hsz];    // hidden states, bf16
__device__ __nv_bfloat16  g_Woutb[32000 * 1024];       // W_out in bf16

// ----------------------------- helpers -------------------------------------
__device__ __forceinline__ float tanhx(float x) {           // ~1e-6 rel err
    float xx = fminf(fmaxf(x, -15.f), 15.f);
    float e = __expf(2.f * xx);
    return __fdividef(e - 1.f, e + 1.f);
}
__device__ __forceinline__ float sigx(float x) {
    float xx = fminf(fmaxf(x, -30.f), 30.f);
    return __fdividef(1.f, 1.f + __expf(-xx));
}
__device__ __forceinline__ void split_tf32(float x, uint32_t& hi, uint32_t& lo) {
    asm("cvt.rna.tf32.f32 %0, %1;" : "=r"(hi) : "f"(x));
    float hf = __uint_as_float(hi);
    asm("cvt.rna.tf32.f32 %0, %1;" : "=r"(lo) : "f"(x - hf));
}
__device__ __forceinline__ void mma_tf32(float* c, const uint32_t* a, const uint32_t* b) {
    asm volatile(
        "mma.sync.aligned.m16n8k8.row.col.f32.tf32.tf32.f32 "
        "{%0,%1,%2,%3}, {%4,%5,%6,%7}, {%8,%9}, {%0,%1,%2,%3};"
        : "+f"(c[0]), "+f"(c[1]), "+f"(c[2]), "+f"(c[3])
        : "r"(a[0]), "r"(a[1]), "r"(a[2]), "r"(a[3]), "r"(b[0]), "r"(b[1]));
}
__device__ __forceinline__ void mma_bf16(float* c, const uint32_t* a, const uint32_t* b) {
    asm volatile(
        "mma.sync.aligned.m16n8k16.row.col.f32.bf16.bf16.f32 "
        "{%0,%1,%2,%3}, {%4,%5,%6,%7}, {%8,%9}, {%0,%1,%2,%3};"
        : "+f"(c[0]), "+f"(c[1]), "+f"(c[2]), "+f"(c[3])
        : "r"(a[0]), "r"(a[1]), "r"(a[2]), "r"(a[3]), "r"(b[0]), "r"(b[1]));
}
__device__ __forceinline__ void cpa16(void* dst, const void* src) {
    uint32_t d = (uint32_t)__cvta_generic_to_shared(dst);
    asm volatile("cp.async.ca.shared.global [%0], [%1], 16;" :: "r"(d), "l"(src));
}
__device__ __forceinline__ void cpa_commit() {
    asm volatile("cp.async.commit_group;");
}
template<int N> __device__ __forceinline__ void cpa_wait() {
    asm volatile("cp.async.wait_group %0;" :: "n"(N));
}

// ----------------------------- setup ---------------------------------------
// Wa,W_hh -> g_Wcat ; encoder_hidden -> g_h ; W_out -> bf16
__global__ void setup_kernel(const float* __restrict__ Wa, const float* __restrict__ Whh,
                             const float* __restrict__ ehid, const float* __restrict__ Wout)
{
    long i = (long)blockIdx.x * 256 + threadIdx.x;
    if (i < 4194304L) {
        g_Wcat[i] = (i < 1048576L) ? Wa[i] : Whh[i - 1048576L];
    } else if (i < 4259840L) {
        long j = i - 4194304L; g_h[j] = ehid[j];
    } else if (i < 37027840L) {
        long j = i - 4259840L; g_Woutb[j] = __float2bfloat16(Wout[j]);
    }
}

// ----------------------------- 3xTF32 GEMM ---------------------------------
// C[M,N] = A[M,K] @ B[N,K]^T (+bias when gridDim.z==1), near-fp32 accuracy.
// Split-K over blockIdx.z -> output slab z at C + z*M*N (consumer sums slabs).
// BM=BN=64, BK=32, 128 threads. M,N mult of 64; K/gridDim.z mult of 32.
__global__ void __launch_bounds__(128) gemm_tf32x3(
    const float* __restrict__ A, const float* __restrict__ B,
    const float* __restrict__ bias, float* __restrict__ Cbase,
    int M, int N, int K)
{
    __shared__ __align__(16) float As[64][36];
    __shared__ __align__(16) float Bs[64][36];
    int tid  = threadIdx.x;
    int warp = tid >> 5, lane = tid & 31;
    int wm = warp >> 1, wn = warp & 1;
    int bm = blockIdx.x * 64, bn = blockIdx.y * 64;
    int kc = K / gridDim.z;
    int k0 = blockIdx.z * kc;
    float* C = Cbase + (long)blockIdx.z * M * N;

    float c[2][4][4];
#pragma unroll
    for (int i = 0; i < 2; i++)
#pragma unroll
        for (int j = 0; j < 4; j++)
#pragma unroll
            for (int r = 0; r < 4; r++) c[i][j][r] = 0.f;

    int lr = tid >> 1;
    int lc = (tid & 1) * 16;
    const float* Ag = A + (long)(bm + lr) * K + k0 + lc;
    const float* Bg = B + (long)(bn + lr) * K + k0 + lc;

    for (int kt = 0; kt < kc; kt += 32) {
#pragma unroll
        for (int u = 0; u < 4; u++) {
            *(float4*)&As[lr][lc + u * 4] = *(const float4*)(Ag + kt + u * 4);
            *(float4*)&Bs[lr][lc + u * 4] = *(const float4*)(Bg + kt + u * 4);
        }
        __syncthreads();
#pragma unroll
        for (int ks = 0; ks < 4; ks++) {
            int kb = ks * 8;
            uint32_t ahi[2][4], alo[2][4], bhi[4][2], blo[4][2];
#pragma unroll
            for (int i = 0; i < 2; i++) {
                int r0 = wm * 32 + i * 16 + (lane >> 2);
                int cc = kb + (lane & 3);
                split_tf32(As[r0    ][cc    ], ahi[i][0], alo[i][0]);
                split_tf32(As[r0 + 8][cc    ], ahi[i][1], alo[i][1]);
                split_tf32(As[r0    ][cc + 4], ahi[i][2], alo[i][2]);
                split_tf32(As[r0 + 8][cc + 4], ahi[i][3], alo[i][3]);
            }
#pragma unroll
            for (int j = 0; j < 4; j++) {
                int n0 = wn * 32 + j * 8 + (lane >> 2);
                int kk = kb + (lane & 3);
                split_tf32(Bs[n0][kk    ], bhi[j][0], blo[j][0]);
                split_tf32(Bs[n0][kk + 4], bhi[j][1], blo[j][1]);
            }
#pragma unroll
            for (int i = 0; i < 2; i++)
#pragma unroll
                for (int j = 0; j < 4; j++) {
                    mma_tf32(c[i][j], ahi[i], bhi[j]);
                    mma_tf32(c[i][j], alo[i], bhi[j]);
                    mma_tf32(c[i][j], ahi[i], blo[j]);
                }
        }
        __syncthreads();
    }

#pragma unroll
    for (int i = 0; i < 2; i++) {
        int r0 = bm + wm * 32 + i * 16 + (lane >> 2);
#pragma unroll
        for (int j = 0; j < 4; j++) {
            int c0 = bn + wn * 32 + j * 8 + (lane & 3) * 2;
            float b0 = bias ? bias[c0]     : 0.f;
            float b1 = bias ? bias[c0 + 1] : 0.f;
            C[(long)r0 * N + c0]           = c[i][j][0] + b0;
            C[(long)r0 * N + c0 + 1]       = c[i][j][1] + b1;
            C[(long)(r0 + 8) * N + c0]     = c[i][j][2] + b0;
            C[(long)(r0 + 8) * N + c0 + 1] = c[i][j][3] + b1;
        }
    }
}

// ----------------------------- attention + embed ---------------------------
__global__ void __launch_bounds__(256) attn_kernel(
    const float* __restrict__ enc, const float* __restrict__ Va,
    const float* __restrict__ bv, const int* __restrict__ target,
    const float* __restrict__ emb, const float* __restrict__ ba,
    float* __restrict__ out_attn, int t)
{
    int b = blockIdx.x, tid = threadIdx.x;
    __shared__ float qs[Hsz];
    __shared__ float sc[Ssz];
    for (int h = tid; h < Hsz; h += 256) {
        float q = ba[h];
#pragma unroll
        for (int z = 0; z < KS; z++) q += g_qgh[z * (Bsz * 4096) + b * 4096 + h];
        qs[h] = q;
    }
    __syncthreads();

    int warp = tid >> 5, lane = tid & 31;
    for (int s = warp; s < Ssz; s += 8) {
        const float* kr = g_keysU + ((long)b * Ssz + s) * Hsz;
        float acc = 0.f;
        for (int h = lane; h < Hsz; h += 32)
            acc += tanhx(qs[h] + kr[h]) * Va[h];
        for (int o = 16; o; o >>= 1) acc += __shfl_xor_sync(~0u, acc, o);
        if (lane == 0) sc[s] = acc + bv[0];
    }
    __syncthreads();

    if (warp == 0) {
        float v0 = sc[lane], v1 = sc[lane + 32];
        float m = fmaxf(v0, v1);
        for (int o = 16; o; o >>= 1) m = fmaxf(m, __shfl_xor_sync(~0u, m, o));
        float e0 = __expf(v0 - m), e1 = __expf(v1 - m);
        float ssum = e0 + e1;
        for (int o = 16; o; o >>= 1) ssum += __shfl_xor_sync(~0u, ssum, o);
        float inv = 1.f / ssum;
        sc[lane] = e0 * inv; sc[lane + 32] = e1 * inv;
        long ob = ((long)b * Tsz + t) * Ssz;
        out_attn[ob + lane]      = e0 * inv;
        out_attn[ob + lane + 32] = e1 * inv;
    }
    __syncthreads();

    int h0 = tid * 4;
    float4 acc = {0.f, 0.f, 0.f, 0.f};
    const float* eb = enc + (long)b * Ssz * Hsz + h0;
#pragma unroll 4
    for (int s = 0; s < Ssz; s++) {
        float w = sc[s];
        float4 e = *(const float4*)(eb + (long)s * Hsz);
        acc.x += w * e.x; acc.y += w * e.y; acc.z += w * e.z; acc.w += w * e.w;
    }
    *(float4*)&g_x[b * 2048 + Hsz + h0] = acc;

    int tok = (t == 0) ? 0 : target[b * Tsz + (t - 1)];
    *(float4*)&g_x[b * 2048 + h0] = *(const float4*)(emb + (long)tok * Hsz + h0);
}

// ----------------------------- GRU gates -----------------------------------
__global__ void __launch_bounds__(256) gates_kernel(
    const float* __restrict__ b_ih, const float* __restrict__ b_hh,
    float* __restrict__ out_hidden, int t)
{
    int b = blockIdx.x, tid = threadIdx.x;
    const int QS = Bsz * 4096, GS = Bsz * 3072;
    for (int h = tid; h < Hsz; h += 256) {
        float ir = b_ih[h], iz = b_ih[1024 + h], in_ = b_ih[2048 + h];
        float hr = b_hh[h], hz = b_hh[1024 + h], hn = b_hh[2048 + h];
#pragma unroll
        for (int z = 0; z < KS; z++) {
            ir  += g_gi [z * GS + b * 3072 + h];
            iz  += g_gi [z * GS + b * 3072 + 1024 + h];
            in_ += g_gi [z * GS + b * 3072 + 2048 + h];
            hr  += g_qgh[z * QS + b * 4096 + 1024 + h];
            hz  += g_qgh[z * QS + b * 4096 + 2048 + h];
            hn  += g_qgh[z * QS + b * 4096 + 3072 + h];
        }
        float r = sigx(ir + hr);
        float z_ = sigx(iz + hz);
        float n = tanhx(in_ + r * hn);
        float hnew = (1.f - z_) * n + z_ * g_h[b * Hsz + h];
        g_h[b * Hsz + h] = hnew;
        g_Hall[((long)b * Tsz + t) * Hsz + h] = __float2bfloat16(hnew);
        if (t == Tsz - 1) out_hidden[b * Hsz + h] = hnew;
    }
}

// ----------------------------- bf16 logits GEMM ----------------------------
// C[M,N] = A[M,K] @ B[N,K]^T + bias. BM=BN=128, BK=16, 3-stage cp.async.
// 256 threads (8 warps, 4x2). M%128==0, N%128==0, K%16==0.
__global__ void __launch_bounds__(256) gemm_bf16_big(
    const __nv_bfloat16* __restrict__ A, const __nv_bfloat16* __restrict__ B,
    const float* __restrict__ bias, float* __restrict__ C,
    int M, int N, int K)
{
    __shared__ __align__(16) __nv_bfloat16 As[3][128][24];
    __shared__ __align__(16) __nv_bfloat16 Bs[3][128][24];
    int tid  = threadIdx.x;
    int warp = tid >> 5, lane = tid & 31;
    int wm = warp >> 1, wn = warp & 1;
    int bm = blockIdx.x * 128, bn = blockIdx.y * 128;
    int NT = K >> 4;

    float c[2][8][4];
#pragma unroll
    for (int i = 0; i < 2; i++)
#pragma unroll
        for (int j = 0; j < 8; j++)
#pragma unroll
            for (int r = 0; r < 4; r++) c[i][j][r] = 0.f;

    // per-thread load slot: 1 chunk (16B = 8 bf16) of A, 1 of B per stage
    int row = tid >> 1, ch = (tid & 1) * 8;
    const __nv_bfloat16* Ag = A + (long)(bm + row) * K + ch;
    const __nv_bfloat16* Bg = B + (long)(bn + row) * K + ch;

#define ISSUE(kt, st) do {                                   \
        cpa16(&As[st][row][ch], Ag + (kt) * 16);             \
        cpa16(&Bs[st][row][ch], Bg + (kt) * 16);             \
        cpa_commit();                                        \
    } while (0)

    ISSUE(0, 0);
    ISSUE(1, 1);

    for (int kt = 0; kt < NT; kt++) {
        if (kt + 1 < NT) cpa_wait<1>(); else cpa_wait<0>();
        __syncthreads();
        int st = kt % 3;

        uint32_t af[2][4];
#pragma unroll
        for (int i = 0; i < 2; i++) {
            int r0 = wm * 32 + i * 16 + (lane >> 2);
            int cb = (lane & 3) * 2;
            af[i][0] = *(const uint32_t*)&As[st][r0    ][cb    ];
            af[i][1] = *(const uint32_t*)&As[st][r0 + 8][cb    ];
            af[i][2] = *(const uint32_t*)&As[st][r0    ][cb + 8];
            af[i][3] = *(const uint32_t*)&As[st][r0 + 8][cb + 8];
        }
#pragma unroll
        for (int j = 0; j < 8; j++) {
            int n0 = wn * 64 + j * 8 + (lane >> 2);
            int cb = (lane & 3) * 2;
            uint32_t bf[2];
            bf[0] = *(const uint32_t*)&Bs[st][n0][cb    ];
            bf[1] = *(const uint32_t*)&Bs[st][n0][cb + 8];
            mma_bf16(c[0][j], af[0], bf);
            mma_bf16(c[1][j], af[1], bf);
        }
        __syncthreads();
        if (kt + 2 < NT) ISSUE(kt + 2, (kt + 2) % 3);
    }
#undef ISSUE

#pragma unroll
    for (int i = 0; i < 2; i++) {
        int r0 = bm + wm * 32 + i * 16 + (lane >> 2);
#pragma unroll
        for (int j = 0; j < 8; j++) {
            int c0 = bn + wn * 64 + j * 8 + (lane & 3) * 2;
            float b0 = bias[c0], b1 = bias[c0 + 1];
            C[(long)r0 * N + c0]           = c[i][j][0] + b0;
            C[(long)r0 * N + c0 + 1]       = c[i][j][1] + b1;
            C[(long)(r0 + 8) * N + c0]     = c[i][j][2] + b0;
            C[(long)(r0 + 8) * N + c0 + 1] = c[i][j][3] + b1;
        }
    }
}

// ----------------------------- log-softmax ---------------------------------
__global__ void __launch_bounds__(256) logsoftmax_kernel(float* __restrict__ logits)
{
    float* p = logits + (long)blockIdx.x * Vsz;
    int tid = threadIdx.x;
    float m = -1e30f, s = 0.f;
    for (int i = tid; i < Vsz; i += 256) {
        float v = p[i];
        if (v > m) { s = s * __expf(m - v) + 1.f; m = v; }
        else       { s += __expf(v - m); }
    }
    __shared__ float sm[256], ss[256];
    sm[tid] = m; ss[tid] = s; __syncthreads();
    for (int o = 128; o; o >>= 1) {
        if (tid < o) {
            float m2 = sm[tid + o], s2 = ss[tid + o];
            float M = fmaxf(sm[tid], m2);
            ss[tid] = ss[tid] * __expf(sm[tid] - M) + s2 * __expf(m2 - M);
            sm[tid] = M;
        }
        __syncthreads();
    }
    float logZ = sm[0] + logf(ss[0]);
    for (int i = tid; i < Vsz; i += 256) p[i] -= logZ;
}

// ----------------------------- launch --------------------------------------
extern "C" void kernel_launch(void* const* d_in, const int* in_sizes, int n_in,
                              void* d_out, int out_size)
{
    (void)in_sizes; (void)n_in; (void)out_size;
    const float* enc   = (const float*)d_in[0];
    const float* ehid  = (const float*)d_in[1];
    const int*   targ  = (const int*)  d_in[2];
    const float* emb   = (const float*)d_in[3];
    const float* Wa    = (const float*)d_in[4];
    const float* ba    = (const float*)d_in[5];
    const float* Ua    = (const float*)d_in[6];
    const float* bu    = (const float*)d_in[7];
    const float* Va    = (const float*)d_in[8];
    const float* bv    = (const float*)d_in[9];
    const float* W_ih  = (const float*)d_in[10];
    const float* W_hh  = (const float*)d_in[11];
    const float* b_ih  = (const float*)d_in[12];
    const float* b_hh  = (const float*)d_in[13];
    const float* W_out = (const float*)d_in[14];
    const float* b_out = (const float*)d_in[15];
    float* out = (float*)d_out;

    float *pWcat, *pkeysU, *ph, *px, *pqgh, *pgi;
    __nv_bfloat16 *pHall, *pWoutb;
    cudaGetSymbolAddress((void**)&pWcat,  g_Wcat);
    cudaGetSymbolAddress((void**)&pkeysU, g_keysU);
    cudaGetSymbolAddress((void**)&ph,     g_h);
    cudaGetSymbolAddress((void**)&px,     g_x);
    cudaGetSymbolAddress((void**)&pqgh,   g_qgh);
    cudaGetSymbolAddress((void**)&pgi,    g_gi);
    cudaGetSymbolAddress((void**)&pHall,  g_Hall);
    cudaGetSymbolAddress((void**)&pWoutb, g_Woutb);

    setup_kernel<<<(37027840 + 255) / 256, 256>>>(Wa, W_hh, ehid, W_out);

    // keysU = enc @ Ua^T + bu : [4096,1024] x [1024,1024]^T, near-fp32
    gemm_tf32x3<<<dim3(64, 16, 1), 128>>>(enc, Ua, bu, pkeysU, 4096, 1024, 1024);

    for (int t = 0; t < Tsz; t++) {
        // [q | gh] = h @ [Wa;W_hh]^T : [64,4096], K=1024, split-K 4
        gemm_tf32x3<<<dim3(1, 64, KS), 128>>>(ph, pWcat, nullptr, pqgh, 64, 4096, 1024);
        attn_kernel<<<Bsz, 256>>>(enc, Va, bv, targ, emb, ba, out + OUT_ATTN, t);
        // gi = x @ W_ih^T : [64,3072], K=2048, split-K 4
        gemm_tf32x3<<<dim3(1, 48, KS), 128>>>(px, W_ih, nullptr, pgi, 64, 3072, 2048);
        gates_kernel<<<Bsz, 256>>>(b_ih, b_hh, out + OUT_HIDDEN, t);
    }

    // logits = H_all @ W_out^T + b_out : [2560, 32000], K=1024, bf16
    gemm_bf16_big<<<dim3(20, 250), 256>>>(pHall, pWoutb, b_out, out + OUT_LOGITS,
                                          2560, 32000, 1024);
    logsoftmax_kernel<<<Bsz * Tsz, 256>>>(out + OUT_LOGITS);
}